// round 16
// baseline (speedup 1.0000x reference)
#include <cuda_runtime.h>
#include <cuda_fp16.h>
#include <float.h>
#include <stdint.h>

// Problem dims (fixed by the reference)
static constexpr int B_  = 32;
static constexpr int TQ  = 1024;
static constexpr int TK  = 1024;
static constexpr int HH  = 512;

// ---------------------------------------------------------------------------
// fp16x3 GEMM, operands pre-split to hi/lo fp16 in gmem.
// C[M,N] = A[M,K]*B[N,K]^T (+bias). CTA 128x128, BK=64 (4 k16 chunks),
// 3-stage cp.async ring, register fragment double-buffering, and PERSISTENT
// CTAs: each CTA processes ~ntiles/grid tiles with the ring rolling across
// tile boundaries (prologue paid once per CTA, epilogue overlapped).
// ---------------------------------------------------------------------------
static constexpr int BM = 128;
static constexpr int BN = 128;
static constexpr int BK = 64;
static constexpr int STAGES = 3;
static constexpr int ROW_BYTES   = 256;                 // 64 hi + 64 lo halves
static constexpr int TILE_BYTES  = 128 * ROW_BYTES;     // 32KB per operand tile
static constexpr int B_OFF       = TILE_BYTES;
static constexpr int STAGE_BYTES = 2 * TILE_BYTES;      // 64KB
static constexpr int SMEM_BYTES  = STAGES * STAGE_BYTES;  // 192KB

// ---- pre-split fp16 scratch (device globals; no allocations) ----
__device__ __half g_qry_hi [(size_t)B_ * TQ * HH];
__device__ __half g_qry_lo [(size_t)B_ * TQ * HH];
__device__ __half g_W_hi   [(size_t)HH * HH];
__device__ __half g_W_lo   [(size_t)HH * HH];
__device__ __half g_keys_hi[(size_t)B_ * TK * HH];
__device__ __half g_keys_lo[(size_t)B_ * TK * HH];
__device__ __half g_keysT_hi[(size_t)B_ * HH * TK];
__device__ __half g_keysT_lo[(size_t)B_ * HH * TK];
__device__ __half g_q_hi   [(size_t)B_ * TQ * HH];
__device__ __half g_q_lo   [(size_t)B_ * TQ * HH];
__device__ __half g_attn_hi[(size_t)B_ * TQ * TK];
__device__ __half g_attn_lo[(size_t)B_ * TQ * TK];

__device__ __forceinline__ uint32_t smem_u32_of(const void* p) {
    uint32_t a;
    asm("{ .reg .u64 t; cvta.to.shared.u64 t, %1; cvt.u32.u64 %0, t; }"
        : "=r"(a) : "l"(p));
    return a;
}

__device__ __forceinline__ void cp_async16(uint32_t dst, const void* src) {
    asm volatile("cp.async.cg.shared.global [%0], [%1], 16;"
                 :: "r"(dst), "l"(src) : "memory");
}
#define CP_COMMIT() asm volatile("cp.async.commit_group;" ::: "memory")
#define CP_WAIT(n)  asm volatile("cp.async.wait_group %0;" :: "n"(n) : "memory")

__device__ __forceinline__ void mma_f16(float* d, const uint32_t* a, const uint32_t* b) {
    asm volatile(
        "mma.sync.aligned.m16n8k16.row.col.f32.f16.f16.f32 "
        "{%0,%1,%2,%3}, {%4,%5,%6,%7}, {%8,%9}, {%0,%1,%2,%3};"
        : "+f"(d[0]), "+f"(d[1]), "+f"(d[2]), "+f"(d[3])
        : "r"(a[0]), "r"(a[1]), "r"(a[2]), "r"(a[3]), "r"(b[0]), "r"(b[1]));
}

__device__ __forceinline__ void ldsm_x4(uint32_t* r, uint32_t saddr) {
    asm volatile("ldmatrix.sync.aligned.m8n8.x4.shared.b16 {%0,%1,%2,%3}, [%4];"
                 : "=r"(r[0]), "=r"(r[1]), "=r"(r[2]), "=r"(r[3]) : "r"(saddr));
}

// ---------------------------------------------------------------------------
// Persistent GEMM kernel. OUT_HILO: write hi/lo fp16 (with bias) vs fp32.
// Tile id t -> z = t / tiles_pb, m0 = ((t%tiles_pb)/nx)*BM, n0 = (t%nx)*BN.
// ---------------------------------------------------------------------------
template <bool ADD_BIAS, bool OUT_HILO>
__global__ __launch_bounds__(256, 1)
void gemm_persist(const __half* __restrict__ Ahi, const __half* __restrict__ Alo,
                  const __half* __restrict__ Bhi, const __half* __restrict__ Blo,
                  const float* __restrict__ bias,
                  float* __restrict__ Cf, __half* __restrict__ Chi, __half* __restrict__ Clo,
                  int M, int N, int K,
                  long long sA, long long sB, long long sC,
                  int ntiles, int nx, int tiles_pb)
{
    extern __shared__ char sm[];
    const uint32_t smem_base = smem_u32_of(sm);

    const int tid  = threadIdx.x;
    const int wid  = tid >> 5;
    const int lane = tid & 31;
    const int grp  = lane >> 2;
    const int quad = lane & 3;

    const int wm = (wid & 1) * 64;
    const int wn = (wid >> 1) * 32;
    const int S  = K / BK;

    // Stage loader: recomputes tile context from tile id (ALU-cheap, reg-cheap).
    auto load_stage = [&](int t, int s, int buf) {
        const int z  = t / tiles_pb;
        const int r  = t % tiles_pb;
        const int m0 = (r / nx) * BM;
        const int n0 = (r % nx) * BN;
        const __half* Ah_g = Ahi + (long long)z * sA + (long long)m0 * K;
        const __half* Al_g = Alo + (long long)z * sA + (long long)m0 * K;
        const __half* Bh_g = Bhi + (long long)z * sB + (long long)n0 * K;
        const __half* Bl_g = Blo + (long long)z * sB + (long long)n0 * K;
        const int k0 = s * BK;
        const uint32_t sb = smem_base + (uint32_t)(buf * STAGE_BYTES);
        #pragma unroll
        for (int i = 0; i < 8; ++i) {
            const int id  = tid + i * 256;
            const int row = id >> 4;
            const int c   = id & 15;
            const __half* src = ((c < 8) ? Ah_g : Al_g)
                              + (long long)row * K + k0 + (c & 7) * 8;
            cp_async16(sb + (uint32_t)(row * ROW_BYTES + ((c & 8) << 4)
                                       + (((c & 7) ^ (row & 7)) << 4)), src);
        }
        #pragma unroll
        for (int i = 0; i < 8; ++i) {
            const int id  = tid + i * 256;
            const int row = id >> 4;
            const int c   = id & 15;
            const __half* src = ((c < 8) ? Bh_g : Bl_g)
                              + (long long)row * K + k0 + (c & 7) * 8;
            cp_async16(sb + (uint32_t)(B_OFF + row * ROW_BYTES + ((c & 8) << 4)
                                       + (((c & 7) ^ (row & 7)) << 4)), src);
        }
    };

    // ---- ldmatrix lane addressing (tile-independent smem offsets) ----
    const int a_rowl = lane & 15;
    const int a_cb   = (lane >> 4) & 1;
    const int b_rowl = (lane & 7) + ((lane & 16) ? 8 : 0);
    const int b_cb   = (lane >> 3) & 1;

    uint32_t a_ro[4]; int a_rm[4];
    #pragma unroll
    for (int mf = 0; mf < 4; ++mf) {
        const int row = wm + mf * 16 + a_rowl;
        a_ro[mf] = (uint32_t)(row * ROW_BYTES);
        a_rm[mf] = row & 7;
    }
    uint32_t b_ro[2]; int b_rm[2];
    #pragma unroll
    for (int np = 0; np < 2; ++np) {
        const int row = wn + np * 16 + b_rowl;
        b_ro[np] = (uint32_t)(B_OFF + row * ROW_BYTES);
        b_rm[np] = row & 7;
    }

    uint32_t ah[2][4][4], al[2][4][4], bhv[2][2][4], blv[2][2][4];

    auto ld_frags = [&](int p, uint32_t sb, int k16) {
        #pragma unroll
        for (int mf = 0; mf < 4; ++mf) {
            const int ch = a_cb + 2 * k16;
            ldsm_x4(ah[p][mf], sb + a_ro[mf] + (uint32_t)((ch ^ a_rm[mf]) << 4));
            ldsm_x4(al[p][mf], sb + a_ro[mf] + 128u + (uint32_t)((ch ^ a_rm[mf]) << 4));
        }
        #pragma unroll
        for (int np = 0; np < 2; ++np) {
            const int ch = b_cb + 2 * k16;
            ldsm_x4(bhv[p][np], sb + b_ro[np] + (uint32_t)((ch ^ b_rm[np]) << 4));
            ldsm_x4(blv[p][np], sb + b_ro[np] + 128u + (uint32_t)((ch ^ b_rm[np]) << 4));
        }
    };

    float acc[4][4][4] = {};

    auto mma_all = [&](int p) {
        #pragma unroll
        for (int mf = 0; mf < 4; ++mf)
            #pragma unroll
            for (int nf = 0; nf < 4; ++nf)
                mma_f16(acc[mf][nf], ah[p][mf], &bhv[p][nf >> 1][(nf & 1) * 2]);
        #pragma unroll
        for (int mf = 0; mf < 4; ++mf)
            #pragma unroll
            for (int nf = 0; nf < 4; ++nf)
                mma_f16(acc[mf][nf], ah[p][mf], &blv[p][nf >> 1][(nf & 1) * 2]);
        #pragma unroll
        for (int mf = 0; mf < 4; ++mf)
            #pragma unroll
            for (int nf = 0; nf < 4; ++nf)
                mma_f16(acc[mf][nf], al[p][mf], &bhv[p][nf >> 1][(nf & 1) * 2]);
    };

    int t = blockIdx.x;
    if (t >= ntiles) return;

    // ---- one-time prologue ----
    load_stage(t, 0, 0); CP_COMMIT();
    load_stage(t, 1, 1); CP_COMMIT();
    CP_WAIT(1);
    __syncthreads();
    ld_frags(0, smem_base, 0);
    int rb = 0;

    while (true) {
        const int tn = t + gridDim.x;
        const bool has_next = (tn < ntiles);

        for (int s = 0; s < S; ++s) {
            const uint32_t sb = smem_base + (uint32_t)(rb * STAGE_BYTES);
            const int ls = s + 2;
            if (ls < S)            load_stage(t,  ls,     (rb + 2) % 3);
            else if (has_next)     load_stage(tn, ls - S, (rb + 2) % 3);
            CP_COMMIT();   // always: keeps wait-group accounting uniform

            ld_frags(1, sb, 1); mma_all(0);
            ld_frags(0, sb, 2); mma_all(1);
            ld_frags(1, sb, 3); mma_all(0);

            CP_WAIT(1);
            if (s + 1 < S || has_next)
                ld_frags(0, smem_base + (uint32_t)(((rb + 1) % 3) * STAGE_BYTES), 0);
            __syncthreads();
            mma_all(1);
            rb = (rb + 1) % 3;
        }

        // ---- epilogue for tile t (next tile's loads already in flight) ----
        {
            const int z  = t / tiles_pb;
            const int r0t = t % tiles_pb;
            const int m0 = (r0t / nx) * BM;
            const int n0 = (r0t % nx) * BN;
            const long long coff = (long long)z * sC;
            #pragma unroll
            for (int mf = 0; mf < 4; ++mf) {
                #pragma unroll
                for (int nf = 0; nf < 4; ++nf) {
                    const int rr = m0 + wm + mf * 16 + grp;
                    const int cc = n0 + wn + nf * 8 + quad * 2;
                    float v0 = acc[mf][nf][0], v1 = acc[mf][nf][1];
                    float v2 = acc[mf][nf][2], v3 = acc[mf][nf][3];
                    if (ADD_BIAS) {
                        const float b0 = bias[cc], b1 = bias[cc + 1];
                        v0 += b0; v1 += b1; v2 += b0; v3 += b1;
                    }
                    if (OUT_HILO) {
                        const long long o0 = (long long)rr * N + cc + coff;
                        const long long o1 = (long long)(rr + 8) * N + cc + coff;
                        __half2 h0 = __floats2half2_rn(v0, v1);
                        __half2 l0 = __floats2half2_rn(v0 - __low2float(h0), v1 - __high2float(h0));
                        *(__half2*)(Chi + o0) = h0;
                        *(__half2*)(Clo + o0) = l0;
                        __half2 h1 = __floats2half2_rn(v2, v3);
                        __half2 l1 = __floats2half2_rn(v2 - __low2float(h1), v3 - __high2float(h1));
                        *(__half2*)(Chi + o1) = h1;
                        *(__half2*)(Clo + o1) = l1;
                    } else {
                        float* Cb = Cf + coff;
                        float2 w0; w0.x = v0; w0.y = v1;
                        float2 w1; w1.x = v2; w1.y = v3;
                        *(float2*)(Cb + (long long)rr * N + cc) = w0;
                        *(float2*)(Cb + (long long)(rr + 8) * N + cc) = w1;
                    }
                }
            }
        }

        if (!has_next) break;
        #pragma unroll
        for (int mf = 0; mf < 4; ++mf)
            #pragma unroll
            for (int nf = 0; nf < 4; ++nf)
                #pragma unroll
                for (int c = 0; c < 4; ++c)
                    acc[mf][nf][c] = 0.0f;
        t = tn;
    }
}

// ---------------------------------------------------------------------------
// query + W fp32 -> hi/lo fp16 split (one launch).
// ---------------------------------------------------------------------------
__global__ __launch_bounds__(256)
void split_qw(const float* __restrict__ query, const float* __restrict__ W,
              __half* __restrict__ qhi, __half* __restrict__ qlo,
              __half* __restrict__ whi, __half* __restrict__ wlo)
{
    const long long n4q = (long long)B_ * TQ * HH / 4;
    const long long n4w = (long long)HH * HH / 4;
    const long long i = (long long)blockIdx.x * 256 + threadIdx.x;
    const float* in; __half* hi; __half* lo; long long j;
    if (i < n4q)            { in = query; hi = qhi; lo = qlo; j = i; }
    else if (i < n4q + n4w) { in = W;     hi = whi; lo = wlo; j = i - n4q; }
    else return;
    float4 v = ((const float4*)in)[j];
    __half2 h01 = __floats2half2_rn(v.x, v.y);
    __half2 h23 = __floats2half2_rn(v.z, v.w);
    __half2 l01 = __floats2half2_rn(v.x - __low2float(h01), v.y - __high2float(h01));
    __half2 l23 = __floats2half2_rn(v.z - __low2float(h23), v.w - __high2float(h23));
    ((__half2*)hi)[j * 2]     = h01;
    ((__half2*)hi)[j * 2 + 1] = h23;
    ((__half2*)lo)[j * 2]     = l01;
    ((__half2*)lo)[j * 2 + 1] = l23;
}

// ---------------------------------------------------------------------------
// keys -> keys hi/lo [B,Tk,H]  +  keysT hi/lo [B,H,Tk]
// ---------------------------------------------------------------------------
__global__ __launch_bounds__(256)
void split_keys_all(const float* __restrict__ keys,
                    __half* __restrict__ khi, __half* __restrict__ klo,
                    __half* __restrict__ kThi, __half* __restrict__ kTlo)
{
    __shared__ float tile[32][33];
    const int b  = blockIdx.z;
    const int t0 = blockIdx.x * 32;
    const int h0 = blockIdx.y * 32;
    const int tx = threadIdx.x;
    const int ty = threadIdx.y;
    const float* inb = keys + (long long)b * TK * HH;
    __half* khb  = khi  + (long long)b * TK * HH;
    __half* klb  = klo  + (long long)b * TK * HH;
    __half* kThb = kThi + (long long)b * HH * TK;
    __half* kTlb = kTlo + (long long)b * HH * TK;

    #pragma unroll
    for (int i = 0; i < 32; i += 8) {
        float v = inb[(long long)(t0 + ty + i) * HH + h0 + tx];
        tile[ty + i][tx] = v;
        __half h = __float2half_rn(v);
        khb[(long long)(t0 + ty + i) * HH + h0 + tx] = h;
        klb[(long long)(t0 + ty + i) * HH + h0 + tx] = __float2half_rn(v - __half2float(h));
    }
    __syncthreads();
    #pragma unroll
    for (int i = 0; i < 32; i += 8) {
        float v = tile[tx][ty + i];
        __half h = __float2half_rn(v);
        kThb[(long long)(h0 + ty + i) * TK + t0 + tx] = h;
        kTlb[(long long)(h0 + ty + i) * TK + t0 + tx] = __float2half_rn(v - __half2float(h));
    }
}

// ---------------------------------------------------------------------------
// In-place row softmax over TK=1024; also emits hi/lo fp16 copy.
// ---------------------------------------------------------------------------
__global__ __launch_bounds__(256)
void softmax_rows(float* __restrict__ attn, __half* __restrict__ ahi,
                  __half* __restrict__ alo)
{
    const long long row = blockIdx.x;
    float* p = attn + row * (long long)TK;
    const int tid = threadIdx.x;

    float4 v = reinterpret_cast<float4*>(p)[tid];
    __shared__ float sred[8];

    float m = fmaxf(fmaxf(v.x, v.y), fmaxf(v.z, v.w));
    #pragma unroll
    for (int o = 16; o > 0; o >>= 1)
        m = fmaxf(m, __shfl_xor_sync(0xffffffffu, m, o));
    if ((tid & 31) == 0) sred[tid >> 5] = m;
    __syncthreads();
    if (tid < 32) {
        float t = (tid < 8) ? sred[tid] : -FLT_MAX;
        #pragma unroll
        for (int o = 4; o > 0; o >>= 1)
            t = fmaxf(t, __shfl_xor_sync(0xffffffffu, t, o));
        if (tid == 0) sred[0] = t;
    }
    __syncthreads();
    const float mx = sred[0];
    __syncthreads();

    v.x = __expf(v.x - mx);
    v.y = __expf(v.y - mx);
    v.z = __expf(v.z - mx);
    v.w = __expf(v.w - mx);
    float s = v.x + v.y + v.z + v.w;
    #pragma unroll
    for (int o = 16; o > 0; o >>= 1)
        s += __shfl_xor_sync(0xffffffffu, s, o);
    if ((tid & 31) == 0) sred[tid >> 5] = s;
    __syncthreads();
    if (tid < 32) {
        float t = (tid < 8) ? sred[tid] : 0.0f;
        #pragma unroll
        for (int o = 4; o > 0; o >>= 1)
            t += __shfl_xor_sync(0xffffffffu, t, o);
        if (tid == 0) sred[0] = t;
    }
    __syncthreads();
    const float inv = 1.0f / sred[0];

    v.x *= inv; v.y *= inv; v.z *= inv; v.w *= inv;
    reinterpret_cast<float4*>(p)[tid] = v;

    __half2 h01 = __floats2half2_rn(v.x, v.y);
    __half2 h23 = __floats2half2_rn(v.z, v.w);
    __half2 l01 = __floats2half2_rn(v.x - __low2float(h01), v.y - __high2float(h01));
    __half2 l23 = __floats2half2_rn(v.z - __low2float(h23), v.w - __high2float(h23));
    __half2* hp = (__half2*)(ahi + row * (long long)TK) + tid * 2;
    __half2* lp = (__half2*)(alo + row * (long long)TK) + tid * 2;
    hp[0] = h01; hp[1] = h23;
    lp[0] = l01; lp[1] = l23;
}

// ---------------------------------------------------------------------------
// Launch. Inputs: query [B,Tq,H], keys [B,Tk,H], W [H,H], b [H]
// Output: context [B,Tq,H] then attn_weights [B,Tq,Tk].
// ---------------------------------------------------------------------------
extern "C" void kernel_launch(void* const* d_in, const int* in_sizes, int n_in,
                              void* d_out, int out_size)
{
    const float* query = (const float*)d_in[0];
    const float* keys  = (const float*)d_in[1];
    const float* W     = (const float*)d_in[2];
    const float* bias  = (const float*)d_in[3];

    float* ctx  = (float*)d_out;                     // [B,Tq,H]
    float* attn = ctx + (long long)B_ * TQ * HH;     // [B,Tq,Tk]

    __half *qry_hi, *qry_lo, *W_hi, *W_lo, *keys_hi, *keys_lo;
    __half *keysT_hi, *keysT_lo, *q_hi, *q_lo, *attn_hi, *attn_lo;
    cudaGetSymbolAddress((void**)&qry_hi,  g_qry_hi);
    cudaGetSymbolAddress((void**)&qry_lo,  g_qry_lo);
    cudaGetSymbolAddress((void**)&W_hi,    g_W_hi);
    cudaGetSymbolAddress((void**)&W_lo,    g_W_lo);
    cudaGetSymbolAddress((void**)&keys_hi, g_keys_hi);
    cudaGetSymbolAddress((void**)&keys_lo, g_keys_lo);
    cudaGetSymbolAddress((void**)&keysT_hi, g_keysT_hi);
    cudaGetSymbolAddress((void**)&keysT_lo, g_keysT_lo);
    cudaGetSymbolAddress((void**)&q_hi,    g_q_hi);
    cudaGetSymbolAddress((void**)&q_lo,    g_q_lo);
    cudaGetSymbolAddress((void**)&attn_hi, g_attn_hi);
    cudaGetSymbolAddress((void**)&attn_lo, g_attn_lo);

    cudaFuncSetAttribute((const void*)gemm_persist<true, true>,
                         cudaFuncAttributeMaxDynamicSharedMemorySize, SMEM_BYTES);
    cudaFuncSetAttribute((const void*)gemm_persist<false, false>,
                         cudaFuncAttributeMaxDynamicSharedMemorySize, SMEM_BYTES);

    int nsm = 148;
    cudaDeviceGetAttribute(&nsm, cudaDevAttrMultiProcessorCount, 0);

    // 0) splits
    {
        const long long n4 = (long long)B_ * TQ * HH / 4 + (long long)HH * HH / 4;
        split_qw<<<(unsigned)((n4 + 255) / 256), 256>>>(
            query, W, qry_hi, qry_lo, W_hi, W_lo);
        split_keys_all<<<dim3(TK / 32, HH / 32, B_), dim3(32, 8)>>>(
            keys, keys_hi, keys_lo, keysT_hi, keysT_lo);
    }

    // 1) q = query @ W^T + b -> q hi/lo fp16   (M=32768, N=512, K=512)
    {
        const int nx = HH / BN;                       // 4
        const int ntiles = (B_ * TQ / BM) * nx;       // 1024
        const int grid = ntiles < nsm ? ntiles : nsm;
        gemm_persist<true, true><<<grid, 256, SMEM_BYTES>>>(
            qry_hi, qry_lo, W_hi, W_lo, bias,
            nullptr, q_hi, q_lo,
            B_ * TQ, HH, HH, 0, 0, 0,
            ntiles, nx, ntiles /* single batch: tiles_pb = ntiles */);
    }

    // 2) scores = q @ keys^T per batch -> attn fp32   (M=1024, N=1024, K=512)
    {
        const int nx = TK / BN;                       // 8
        const int tiles_pb = (TQ / BM) * nx;          // 64
        const int ntiles = tiles_pb * B_;             // 2048
        const int grid = ntiles < nsm ? ntiles : nsm;
        gemm_persist<false, false><<<grid, 256, SMEM_BYTES>>>(
            q_hi, q_lo, keys_hi, keys_lo, nullptr,
            attn, nullptr, nullptr,
            TQ, TK, HH,
            (long long)TQ * HH, (long long)TK * HH, (long long)TQ * TK,
            ntiles, nx, tiles_pb);
    }

    // 3) softmax rows in place + emit hi/lo fp16
    softmax_rows<<<B_ * TQ, 256>>>(attn, attn_hi, attn_lo);

    // 4) context = attn @ keysT^T per batch -> ctx fp32   (M=1024, N=512, K=1024)
    {
        const int nx = HH / BN;                       // 4
        const int tiles_pb = (TQ / BM) * nx;          // 32
        const int ntiles = tiles_pb * B_;             // 1024
        const int grid = ntiles < nsm ? ntiles : nsm;
        gemm_persist<false, false><<<grid, 256, SMEM_BYTES>>>(
            attn_hi, attn_lo, keysT_hi, keysT_lo, nullptr,
            ctx, nullptr, nullptr,
            TQ, HH, TK,
            (long long)TQ * TK, (long long)HH * TK, (long long)TQ * HH,
            ntiles, nx, tiles_pb);
    }
}

// round 17
// speedup vs baseline: 1.0556x; 1.0556x over previous
#include <cuda_runtime.h>
#include <cuda_fp16.h>
#include <float.h>
#include <stdint.h>

// Problem dims (fixed by the reference)
static constexpr int B_  = 32;
static constexpr int TQ  = 1024;
static constexpr int TK  = 1024;
static constexpr int HH  = 512;

// ---------------------------------------------------------------------------
// fp16x3 GEMM (R15 config — best measured: tensor 74%).
// CTA 128x128, BK=64 (4 k16 chunks), 3-stage cp.async ring (192KB),
// register-level fragment double-buffering.
// ---------------------------------------------------------------------------
static constexpr int BM = 128;
static constexpr int BN = 128;
static constexpr int BK = 64;
static constexpr int STAGES = 3;
static constexpr int ROW_BYTES   = 256;
static constexpr int TILE_BYTES  = 128 * ROW_BYTES;     // 32KB per operand tile
static constexpr int B_OFF       = TILE_BYTES;
static constexpr int STAGE_BYTES = 2 * TILE_BYTES;      // 64KB
static constexpr int SMEM_BYTES  = STAGES * STAGE_BYTES;  // 192KB

// ---- pre-split fp16 scratch (device globals; no allocations) ----
__device__ __half g_qry_hi [(size_t)B_ * TQ * HH];
__device__ __half g_qry_lo [(size_t)B_ * TQ * HH];
__device__ __half g_W_hi   [(size_t)HH * HH];
__device__ __half g_W_lo   [(size_t)HH * HH];
__device__ __half g_keys_hi[(size_t)B_ * TK * HH];
__device__ __half g_keys_lo[(size_t)B_ * TK * HH];
__device__ __half g_keysT_hi[(size_t)B_ * HH * TK];
__device__ __half g_keysT_lo[(size_t)B_ * HH * TK];
__device__ __half g_q_hi   [(size_t)B_ * TQ * HH];
__device__ __half g_q_lo   [(size_t)B_ * TQ * HH];
__device__ __half g_attn_hi[(size_t)B_ * TQ * TK];
__device__ __half g_attn_lo[(size_t)B_ * TQ * TK];

__device__ __forceinline__ uint32_t smem_u32_of(const void* p) {
    uint32_t a;
    asm("{ .reg .u64 t; cvta.to.shared.u64 t, %1; cvt.u32.u64 %0, t; }"
        : "=r"(a) : "l"(p));
    return a;
}

__device__ __forceinline__ void cp_async16(uint32_t dst, const void* src) {
    asm volatile("cp.async.cg.shared.global [%0], [%1], 16;"
                 :: "r"(dst), "l"(src) : "memory");
}
#define CP_COMMIT() asm volatile("cp.async.commit_group;" ::: "memory")
#define CP_WAIT(n)  asm volatile("cp.async.wait_group %0;" :: "n"(n) : "memory")

__device__ __forceinline__ void mma_f16(float* d, const uint32_t* a, const uint32_t* b) {
    asm volatile(
        "mma.sync.aligned.m16n8k16.row.col.f32.f16.f16.f32 "
        "{%0,%1,%2,%3}, {%4,%5,%6,%7}, {%8,%9}, {%0,%1,%2,%3};"
        : "+f"(d[0]), "+f"(d[1]), "+f"(d[2]), "+f"(d[3])
        : "r"(a[0]), "r"(a[1]), "r"(a[2]), "r"(a[3]), "r"(b[0]), "r"(b[1]));
}

__device__ __forceinline__ void ldsm_x4(uint32_t* r, uint32_t saddr) {
    asm volatile("ldmatrix.sync.aligned.m8n8.x4.shared.b16 {%0,%1,%2,%3}, [%4];"
                 : "=r"(r[0]), "=r"(r[1]), "=r"(r[2]), "=r"(r[3]) : "r"(saddr));
}

// ---------------------------------------------------------------------------
// GEMM kernel (identical to R15). OUT_HILO: write hi/lo fp16 (+bias) vs fp32.
// ---------------------------------------------------------------------------
template <bool ADD_BIAS, bool OUT_HILO>
__global__ __launch_bounds__(256, 1)
void gemm_hilo(const __half* __restrict__ Ahi, const __half* __restrict__ Alo,
               const __half* __restrict__ Bhi, const __half* __restrict__ Blo,
               const float* __restrict__ bias,
               float* __restrict__ Cf, __half* __restrict__ Chi, __half* __restrict__ Clo,
               int M, int N, int K,
               long long sA, long long sB, long long sC)
{
    extern __shared__ char sm[];
    const uint32_t smem_base = smem_u32_of(sm);

    const int tid  = threadIdx.x;
    const int wid  = tid >> 5;
    const int lane = tid & 31;
    const int grp  = lane >> 2;
    const int quad = lane & 3;

    const int wm = (wid & 1) * 64;
    const int wn = (wid >> 1) * 32;

    const __half* Ah_g = Ahi + (long long)blockIdx.z * sA;
    const __half* Al_g = Alo + (long long)blockIdx.z * sA;
    const __half* Bh_g = Bhi + (long long)blockIdx.z * sB;
    const __half* Bl_g = Blo + (long long)blockIdx.z * sB;
    const int m0 = blockIdx.y * BM;
    const int n0 = blockIdx.x * BN;
    const int S  = K / BK;

    auto load_stage = [&](int s, int buf) {
        const int k0 = s * BK;
        const uint32_t sb = smem_base + (uint32_t)(buf * STAGE_BYTES);
        #pragma unroll
        for (int i = 0; i < 8; ++i) {
            const int id  = tid + i * 256;
            const int row = id >> 4;
            const int c   = id & 15;
            const __half* src = ((c < 8) ? Ah_g : Al_g)
                              + (long long)(m0 + row) * K + k0 + (c & 7) * 8;
            cp_async16(sb + (uint32_t)(row * ROW_BYTES + ((c & 8) << 4)
                                       + (((c & 7) ^ (row & 7)) << 4)), src);
        }
        #pragma unroll
        for (int i = 0; i < 8; ++i) {
            const int id  = tid + i * 256;
            const int row = id >> 4;
            const int c   = id & 15;
            const __half* src = ((c < 8) ? Bh_g : Bl_g)
                              + (long long)(n0 + row) * K + k0 + (c & 7) * 8;
            cp_async16(sb + (uint32_t)(B_OFF + row * ROW_BYTES + ((c & 8) << 4)
                                       + (((c & 7) ^ (row & 7)) << 4)), src);
        }
    };

    const int a_rowl = lane & 15;
    const int a_cb   = (lane >> 4) & 1;
    const int b_rowl = (lane & 7) + ((lane & 16) ? 8 : 0);
    const int b_cb   = (lane >> 3) & 1;

    uint32_t a_ro[4]; int a_rm[4];
    #pragma unroll
    for (int mf = 0; mf < 4; ++mf) {
        const int row = wm + mf * 16 + a_rowl;
        a_ro[mf] = (uint32_t)(row * ROW_BYTES);
        a_rm[mf] = row & 7;
    }
    uint32_t b_ro[2]; int b_rm[2];
    #pragma unroll
    for (int np = 0; np < 2; ++np) {
        const int row = wn + np * 16 + b_rowl;
        b_ro[np] = (uint32_t)(B_OFF + row * ROW_BYTES);
        b_rm[np] = row & 7;
    }

    uint32_t ah[2][4][4], al[2][4][4], bhv[2][2][4], blv[2][2][4];

    auto ld_frags = [&](int p, uint32_t sb, int k16) {
        #pragma unroll
        for (int mf = 0; mf < 4; ++mf) {
            const int ch = a_cb + 2 * k16;
            ldsm_x4(ah[p][mf], sb + a_ro[mf] + (uint32_t)((ch ^ a_rm[mf]) << 4));
            ldsm_x4(al[p][mf], sb + a_ro[mf] + 128u + (uint32_t)((ch ^ a_rm[mf]) << 4));
        }
        #pragma unroll
        for (int np = 0; np < 2; ++np) {
            const int ch = b_cb + 2 * k16;
            ldsm_x4(bhv[p][np], sb + b_ro[np] + (uint32_t)((ch ^ b_rm[np]) << 4));
            ldsm_x4(blv[p][np], sb + b_ro[np] + 128u + (uint32_t)((ch ^ b_rm[np]) << 4));
        }
    };

    float acc[4][4][4] = {};

    auto mma_all = [&](int p) {
        #pragma unroll
        for (int mf = 0; mf < 4; ++mf)
            #pragma unroll
            for (int nf = 0; nf < 4; ++nf)
                mma_f16(acc[mf][nf], ah[p][mf], &bhv[p][nf >> 1][(nf & 1) * 2]);
        #pragma unroll
        for (int mf = 0; mf < 4; ++mf)
            #pragma unroll
            for (int nf = 0; nf < 4; ++nf)
                mma_f16(acc[mf][nf], ah[p][mf], &blv[p][nf >> 1][(nf & 1) * 2]);
        #pragma unroll
        for (int mf = 0; mf < 4; ++mf)
            #pragma unroll
            for (int nf = 0; nf < 4; ++nf)
                mma_f16(acc[mf][nf], al[p][mf], &bhv[p][nf >> 1][(nf & 1) * 2]);
    };

    load_stage(0, 0); CP_COMMIT();
    if (S > 1) { load_stage(1, 1); CP_COMMIT(); }
    CP_WAIT(1);
    __syncthreads();
    ld_frags(0, smem_base, 0);

    for (int s = 0; s < S; ++s) {
        const uint32_t sb = smem_base + (uint32_t)((s % STAGES) * STAGE_BYTES);

        if (s + 2 < S) { load_stage(s + 2, (s + 2) % STAGES); CP_COMMIT(); }

        ld_frags(1, sb, 1); mma_all(0);
        ld_frags(0, sb, 2); mma_all(1);
        ld_frags(1, sb, 3); mma_all(0);

        if (s + 1 < S) {
            if (s + 2 < S) { CP_WAIT(1); }
            else           { CP_WAIT(0); }
            ld_frags(0, smem_base + (uint32_t)(((s + 1) % STAGES) * STAGE_BYTES), 0);
        }
        __syncthreads();
        mma_all(1);
    }

    #pragma unroll
    for (int mf = 0; mf < 4; ++mf) {
        #pragma unroll
        for (int nf = 0; nf < 4; ++nf) {
            const int r = m0 + wm + mf * 16 + grp;
            const int c = n0 + wn + nf * 8 + quad * 2;
            float v0 = acc[mf][nf][0], v1 = acc[mf][nf][1];
            float v2 = acc[mf][nf][2], v3 = acc[mf][nf][3];
            if (ADD_BIAS) {
                const float b0 = bias[c], b1 = bias[c + 1];
                v0 += b0; v1 += b1; v2 += b0; v3 += b1;
            }
            if (OUT_HILO) {
                const long long o0 = (long long)r * N + c + (long long)blockIdx.z * sC;
                const long long o1 = (long long)(r + 8) * N + c + (long long)blockIdx.z * sC;
                __half2 h0 = __floats2half2_rn(v0, v1);
                __half2 l0 = __floats2half2_rn(v0 - __low2float(h0), v1 - __high2float(h0));
                *(__half2*)(Chi + o0) = h0;
                *(__half2*)(Clo + o0) = l0;
                __half2 h1 = __floats2half2_rn(v2, v3);
                __half2 l1 = __floats2half2_rn(v2 - __low2float(h1), v3 - __high2float(h1));
                *(__half2*)(Chi + o1) = h1;
                *(__half2*)(Clo + o1) = l1;
            } else {
                float* Cb = Cf + (long long)blockIdx.z * sC;
                float2 w0; w0.x = v0; w0.y = v1;
                float2 w1; w1.x = v2; w1.y = v3;
                *(float2*)(Cb + (long long)r * N + c) = w0;
                *(float2*)(Cb + (long long)(r + 8) * N + c) = w1;
            }
        }
    }
}

// ---------------------------------------------------------------------------
// query + W fp32 -> hi/lo fp16 split (one launch).
// ---------------------------------------------------------------------------
__global__ __launch_bounds__(256)
void split_qw(const float* __restrict__ query, const float* __restrict__ W,
              __half* __restrict__ qhi, __half* __restrict__ qlo,
              __half* __restrict__ whi, __half* __restrict__ wlo)
{
    const long long n4q = (long long)B_ * TQ * HH / 4;
    const long long n4w = (long long)HH * HH / 4;
    const long long i = (long long)blockIdx.x * 256 + threadIdx.x;
    const float* in; __half* hi; __half* lo; long long j;
    if (i < n4q)            { in = query; hi = qhi; lo = qlo; j = i; }
    else if (i < n4q + n4w) { in = W;     hi = whi; lo = wlo; j = i - n4q; }
    else return;
    float4 v = ((const float4*)in)[j];
    __half2 h01 = __floats2half2_rn(v.x, v.y);
    __half2 h23 = __floats2half2_rn(v.z, v.w);
    __half2 l01 = __floats2half2_rn(v.x - __low2float(h01), v.y - __high2float(h01));
    __half2 l23 = __floats2half2_rn(v.z - __low2float(h23), v.w - __high2float(h23));
    ((__half2*)hi)[j * 2]     = h01;
    ((__half2*)hi)[j * 2 + 1] = h23;
    ((__half2*)lo)[j * 2]     = l01;
    ((__half2*)lo)[j * 2 + 1] = l23;
}

// ---------------------------------------------------------------------------
// keys -> keys hi/lo [B,Tk,H]  +  keysT hi/lo [B,H,Tk]
// ---------------------------------------------------------------------------
__global__ __launch_bounds__(256)
void split_keys_all(const float* __restrict__ keys,
                    __half* __restrict__ khi, __half* __restrict__ klo,
                    __half* __restrict__ kThi, __half* __restrict__ kTlo)
{
    __shared__ float tile[32][33];
    const int b  = blockIdx.z;
    const int t0 = blockIdx.x * 32;
    const int h0 = blockIdx.y * 32;
    const int tx = threadIdx.x;
    const int ty = threadIdx.y;
    const float* inb = keys + (long long)b * TK * HH;
    __half* khb  = khi  + (long long)b * TK * HH;
    __half* klb  = klo  + (long long)b * TK * HH;
    __half* kThb = kThi + (long long)b * HH * TK;
    __half* kTlb = kTlo + (long long)b * HH * TK;

    #pragma unroll
    for (int i = 0; i < 32; i += 8) {
        float v = inb[(long long)(t0 + ty + i) * HH + h0 + tx];
        tile[ty + i][tx] = v;
        __half h = __float2half_rn(v);
        khb[(long long)(t0 + ty + i) * HH + h0 + tx] = h;
        klb[(long long)(t0 + ty + i) * HH + h0 + tx] = __float2half_rn(v - __half2float(h));
    }
    __syncthreads();
    #pragma unroll
    for (int i = 0; i < 32; i += 8) {
        float v = tile[tx][ty + i];
        __half h = __float2half_rn(v);
        kThb[(long long)(h0 + ty + i) * TK + t0 + tx] = h;
        kTlb[(long long)(h0 + ty + i) * TK + t0 + tx] = __float2half_rn(v - __half2float(h));
    }
}

// ---------------------------------------------------------------------------
// In-place row softmax over TK=1024; emits hi/lo fp16 with 16B stores.
// 128 threads/row, 8 consecutive floats per thread.
// ---------------------------------------------------------------------------
__global__ __launch_bounds__(128)
void softmax_rows(float* __restrict__ attn, __half* __restrict__ ahi,
                  __half* __restrict__ alo)
{
    const long long row = blockIdx.x;
    float4* p = (float4*)(attn + row * (long long)TK);
    const int tid = threadIdx.x;

    float4 v0 = p[tid * 2];
    float4 v1 = p[tid * 2 + 1];
    __shared__ float sred[4];

    float m = fmaxf(fmaxf(fmaxf(v0.x, v0.y), fmaxf(v0.z, v0.w)),
                    fmaxf(fmaxf(v1.x, v1.y), fmaxf(v1.z, v1.w)));
    #pragma unroll
    for (int o = 16; o > 0; o >>= 1)
        m = fmaxf(m, __shfl_xor_sync(0xffffffffu, m, o));
    if ((tid & 31) == 0) sred[tid >> 5] = m;
    __syncthreads();
    if (tid < 32) {
        float t = (tid < 4) ? sred[tid] : -FLT_MAX;
        #pragma unroll
        for (int o = 2; o > 0; o >>= 1)
            t = fmaxf(t, __shfl_xor_sync(0xffffffffu, t, o));
        if (tid == 0) sred[0] = t;
    }
    __syncthreads();
    const float mx = sred[0];
    __syncthreads();

    v0.x = __expf(v0.x - mx); v0.y = __expf(v0.y - mx);
    v0.z = __expf(v0.z - mx); v0.w = __expf(v0.w - mx);
    v1.x = __expf(v1.x - mx); v1.y = __expf(v1.y - mx);
    v1.z = __expf(v1.z - mx); v1.w = __expf(v1.w - mx);
    float s = v0.x + v0.y + v0.z + v0.w + v1.x + v1.y + v1.z + v1.w;
    #pragma unroll
    for (int o = 16; o > 0; o >>= 1)
        s += __shfl_xor_sync(0xffffffffu, s, o);
    if ((tid & 31) == 0) sred[tid >> 5] = s;
    __syncthreads();
    if (tid < 32) {
        float t = (tid < 4) ? sred[tid] : 0.0f;
        #pragma unroll
        for (int o = 2; o > 0; o >>= 1)
            t += __shfl_xor_sync(0xffffffffu, t, o);
        if (tid == 0) sred[0] = t;
    }
    __syncthreads();
    const float inv = 1.0f / sred[0];

    v0.x *= inv; v0.y *= inv; v0.z *= inv; v0.w *= inv;
    v1.x *= inv; v1.y *= inv; v1.z *= inv; v1.w *= inv;
    p[tid * 2]     = v0;
    p[tid * 2 + 1] = v1;

    __half2 h01 = __floats2half2_rn(v0.x, v0.y);
    __half2 h23 = __floats2half2_rn(v0.z, v0.w);
    __half2 h45 = __floats2half2_rn(v1.x, v1.y);
    __half2 h67 = __floats2half2_rn(v1.z, v1.w);
    uint4 hi;
    hi.x = *(uint32_t*)&h01; hi.y = *(uint32_t*)&h23;
    hi.z = *(uint32_t*)&h45; hi.w = *(uint32_t*)&h67;
    __half2 l01 = __floats2half2_rn(v0.x - __low2float(h01), v0.y - __high2float(h01));
    __half2 l23 = __floats2half2_rn(v0.z - __low2float(h23), v0.w - __high2float(h23));
    __half2 l45 = __floats2half2_rn(v1.x - __low2float(h45), v1.y - __high2float(h45));
    __half2 l67 = __floats2half2_rn(v1.z - __low2float(h67), v1.w - __high2float(h67));
    uint4 lo;
    lo.x = *(uint32_t*)&l01; lo.y = *(uint32_t*)&l23;
    lo.z = *(uint32_t*)&l45; lo.w = *(uint32_t*)&l67;
    ((uint4*)(ahi + row * (long long)TK))[tid] = hi;
    ((uint4*)(alo + row * (long long)TK))[tid] = lo;
}

// ---------------------------------------------------------------------------
// Launch. Inputs: query [B,Tq,H], keys [B,Tk,H], W [H,H], b [H]
// Output: context [B,Tq,H] then attn_weights [B,Tq,Tk].
// keys split runs on a forked capture stream, overlapping G1.
// ---------------------------------------------------------------------------
extern "C" void kernel_launch(void* const* d_in, const int* in_sizes, int n_in,
                              void* d_out, int out_size)
{
    const float* query = (const float*)d_in[0];
    const float* keys  = (const float*)d_in[1];
    const float* W     = (const float*)d_in[2];
    const float* bias  = (const float*)d_in[3];

    float* ctx  = (float*)d_out;                     // [B,Tq,H]
    float* attn = ctx + (long long)B_ * TQ * HH;     // [B,Tq,Tk]

    __half *qry_hi, *qry_lo, *W_hi, *W_lo, *keys_hi, *keys_lo;
    __half *keysT_hi, *keysT_lo, *q_hi, *q_lo, *attn_hi, *attn_lo;
    cudaGetSymbolAddress((void**)&qry_hi,  g_qry_hi);
    cudaGetSymbolAddress((void**)&qry_lo,  g_qry_lo);
    cudaGetSymbolAddress((void**)&W_hi,    g_W_hi);
    cudaGetSymbolAddress((void**)&W_lo,    g_W_lo);
    cudaGetSymbolAddress((void**)&keys_hi, g_keys_hi);
    cudaGetSymbolAddress((void**)&keys_lo, g_keys_lo);
    cudaGetSymbolAddress((void**)&keysT_hi, g_keysT_hi);
    cudaGetSymbolAddress((void**)&keysT_lo, g_keysT_lo);
    cudaGetSymbolAddress((void**)&q_hi,    g_q_hi);
    cudaGetSymbolAddress((void**)&q_lo,    g_q_lo);
    cudaGetSymbolAddress((void**)&attn_hi, g_attn_hi);
    cudaGetSymbolAddress((void**)&attn_lo, g_attn_lo);

    cudaFuncSetAttribute((const void*)gemm_hilo<true, true>,
                         cudaFuncAttributeMaxDynamicSharedMemorySize, SMEM_BYTES);
    cudaFuncSetAttribute((const void*)gemm_hilo<false, false>,
                         cudaFuncAttributeMaxDynamicSharedMemorySize, SMEM_BYTES);

    // Fork stream + events (host objects; created per call, not captured).
    cudaStream_t s2;
    cudaStreamCreateWithFlags(&s2, cudaStreamNonBlocking);
    cudaEvent_t e0, e1;
    cudaEventCreateWithFlags(&e0, cudaEventDisableTiming);
    cudaEventCreateWithFlags(&e1, cudaEventDisableTiming);

    // Fork: keys split on s2, concurrent with split_qw + G1 on the main stream.
    cudaEventRecord(e0, 0);
    cudaStreamWaitEvent(s2, e0, 0);
    split_keys_all<<<dim3(TK / 32, HH / 32, B_), dim3(32, 8), 0, s2>>>(
        keys, keys_hi, keys_lo, keysT_hi, keysT_lo);
    cudaEventRecord(e1, s2);

    // Main stream: query/W split -> G1.
    {
        const long long n4 = (long long)B_ * TQ * HH / 4 + (long long)HH * HH / 4;
        split_qw<<<(unsigned)((n4 + 255) / 256), 256>>>(
            query, W, qry_hi, qry_lo, W_hi, W_lo);
    }
    gemm_hilo<true, true><<<dim3(HH / BN, (B_ * TQ) / BM, 1), 256, SMEM_BYTES>>>(
        qry_hi, qry_lo, W_hi, W_lo, bias,
        nullptr, q_hi, q_lo,
        B_ * TQ, HH, HH, 0, 0, 0);

    // Join: G2 needs the keys split.
    cudaStreamWaitEvent(0, e1, 0);

    // 2) scores = q @ keys^T per batch -> attn fp32
    gemm_hilo<false, false><<<dim3(TK / BN, TQ / BM, B_), 256, SMEM_BYTES>>>(
        q_hi, q_lo, keys_hi, keys_lo, nullptr,
        attn, nullptr, nullptr,
        TQ, TK, HH,
        (long long)TQ * HH, (long long)TK * HH, (long long)TQ * TK);

    // 3) softmax rows in place + emit hi/lo fp16
    softmax_rows<<<B_ * TQ, 128>>>(attn, attn_hi, attn_lo);

    // 4) context = attn @ keysT^T per batch -> ctx fp32
    gemm_hilo<false, false><<<dim3(HH / BN, TQ / BM, B_), 256, SMEM_BYTES>>>(
        attn_hi, attn_lo, keysT_hi, keysT_lo, nullptr,
        ctx, nullptr, nullptr,
        TQ, HH, TK,
        (long long)TQ * TK, (long long)HH * TK, (long long)TQ * HH);
}